// round 10
// baseline (speedup 1.0000x reference)
#include <cuda_runtime.h>
#include <cuda_fp16.h>
#include <cstdint>

#define NN 50000
#define EE 800000
#define GG 1000
#define HH 128
#define LL 3
#define CC 6
#define EPS 1e-5f
#define NBLK 196                       // ceil(NN/256)

// ---------------- scratch (device globals; no allocation) ----------------
__device__ int   g_degi[NN];
__device__ int   g_blocksum[NBLK];
__device__ int   g_blockoff[NBLK];
__device__ int   g_rowptr[NN + 1];
__device__ int   g_cursor[NN];
__device__ int   g_csrsrc[EE];
__device__ float g_dis[NN];
__device__ __half2 g_hsb[NN * 64];   // h * dis[row], fp16 packed
__device__ float g_agg[NN * HH];     // aggregated + self + bias (fp32)
__device__ float g_sum[HH];
__device__ float g_sumsq[HH];
__device__ float g_bnscale[HH];
__device__ float g_bnshift[HH];
__device__ float g_pool[GG * HH];
__device__ float g_cnt[GG];

// ---------------- degree / CSR build ----------------
__global__ void k_zero_degi() {
    int n = blockIdx.x * blockDim.x + threadIdx.x;
    if (n < NN) g_degi[n] = 0;
}

__global__ void k_deg_count(const int* __restrict__ dst) {
    int e = blockIdx.x * blockDim.x + threadIdx.x;
    if (e < EE) atomicAdd(&g_degi[dst[e]], 1);
}

__global__ void k_norm() {
    int n = blockIdx.x * blockDim.x + threadIdx.x;
    if (n < NN) g_dis[n] = rsqrtf((float)g_degi[n] + 1.0f);
}

__global__ void k_blocksum() {
    __shared__ int sh[256];
    int t = threadIdx.x;
    int n = blockIdx.x * 256 + t;
    sh[t] = (n < NN) ? g_degi[n] : 0;
    __syncthreads();
#pragma unroll
    for (int off = 128; off > 0; off >>= 1) {
        if (t < off) sh[t] += sh[t + off];
        __syncthreads();
    }
    if (t == 0) g_blocksum[blockIdx.x] = sh[0];
}

__global__ void k_scanblocks() {
    __shared__ int sh[256];
    int t = threadIdx.x;
    int v = (t < NBLK) ? g_blocksum[t] : 0;
    sh[t] = v;
    __syncthreads();
#pragma unroll
    for (int off = 1; off < 256; off <<= 1) {
        int u = (t >= off) ? sh[t - off] : 0;
        __syncthreads();
        sh[t] += u;
        __syncthreads();
    }
    if (t < NBLK) g_blockoff[t] = sh[t] - v;   // exclusive
    if (t == 0) g_rowptr[NN] = EE;
}

__global__ void k_rowptr() {
    __shared__ int sh[256];
    int t = threadIdx.x;
    int n = blockIdx.x * 256 + t;
    int v = (n < NN) ? g_degi[n] : 0;
    sh[t] = v;
    __syncthreads();
#pragma unroll
    for (int off = 1; off < 256; off <<= 1) {
        int u = (t >= off) ? sh[t - off] : 0;
        __syncthreads();
        sh[t] += u;
        __syncthreads();
    }
    if (n < NN) {
        int excl = g_blockoff[blockIdx.x] + sh[t] - v;
        g_rowptr[n] = excl;
        g_cursor[n] = excl;
    }
}

__global__ void k_fill(const int* __restrict__ src, const int* __restrict__ dst) {
    int e = blockIdx.x * blockDim.x + threadIdx.x;
    if (e < EE) {
        int d = dst[e];
        int pos = atomicAdd(&g_cursor[d], 1);
        g_csrsrc[pos] = src[e];
    }
}

// ---------------- TF32 helpers ----------------
__device__ __forceinline__ uint32_t f2tf32(float x) {
    uint32_t r;
    asm("cvt.rna.tf32.f32 %0, %1;" : "=r"(r) : "f"(x));
    return r;
}

#define MMA_TF32(C, A, B0, B1)                                                 \
    asm volatile("mma.sync.aligned.m16n8k8.row.col.f32.tf32.tf32.f32 "        \
                 "{%0,%1,%2,%3}, {%4,%5,%6,%7}, {%8,%9}, {%0,%1,%2,%3};"      \
                 : "+f"((C)[0]), "+f"((C)[1]), "+f"((C)[2]), "+f"((C)[3])     \
                 : "r"((A)[0]), "r"((A)[1]), "r"((A)[2]), "r"((A)[3]),        \
                   "r"(B0), "r"(B1))

// ---------------- GEMM: g_hsb = fp16( BN?(A)[N,128] @ B[128,128] * dis[row] )
// tf32 3-split tensor GEMM. Block 0 also zeroes BN stat accumulators.
#define AP 20     // A smem row stride
#define BP 136    // B smem row stride
__global__ void __launch_bounds__(256) k_gemm(const float* __restrict__ Ain,
                                              const float* __restrict__ B,
                                              int apply_bn) {
    const float* __restrict__ A = Ain ? Ain : g_agg;
    __shared__ float Asb[128][AP];
    __shared__ float Ass[128][AP];
    __shared__ float Bsb[16][BP];
    __shared__ float Bss[16][BP];

    int row0 = blockIdx.x * 128;
    int t = threadIdx.x;
    if (blockIdx.x == 0 && t < 128) {     // zero BN stats for later k_bnstats
        g_sum[t] = 0.0f;
        g_sumsq[t] = 0.0f;
    }
    int w = t >> 5, lane = t & 31;
    int wr = w & 3, wc = w >> 2;
    int g = lane >> 2, tig = lane & 3;

    float c[2][8][4];
#pragma unroll
    for (int mt = 0; mt < 2; mt++)
#pragma unroll
        for (int nt = 0; nt < 8; nt++)
#pragma unroll
            for (int i = 0; i < 4; i++) c[mt][nt][i] = 0.0f;

    for (int k0 = 0; k0 < 128; k0 += 16) {
#pragma unroll
        for (int i = 0; i < 2; i++) {
            int fi = t + i * 256;        // 0..511
            int r = fi >> 2;             // 4 float4 per row
            int kq = fi & 3;
            int grow = row0 + r;
            float4 v = make_float4(0.f, 0.f, 0.f, 0.f);
            if (grow < NN) v = *(const float4*)&A[grow * 128 + k0 + kq * 4];
            if (apply_bn) {
                float4 sc = ((const float4*)g_bnscale)[(k0 >> 2) + kq];
                float4 sh = ((const float4*)g_bnshift)[(k0 >> 2) + kq];
                v.x = fmaxf(v.x * sc.x + sh.x, 0.f);
                v.y = fmaxf(v.y * sc.y + sh.y, 0.f);
                v.z = fmaxf(v.z * sc.z + sh.z, 0.f);
                v.w = fmaxf(v.w * sc.w + sh.w, 0.f);
            }
            float bx = __uint_as_float(f2tf32(v.x));
            float by = __uint_as_float(f2tf32(v.y));
            float bz = __uint_as_float(f2tf32(v.z));
            float bw = __uint_as_float(f2tf32(v.w));
            int kc = kq * 4;
            Asb[r][kc + 0] = bx;  Ass[r][kc + 0] = __uint_as_float(f2tf32(v.x - bx));
            Asb[r][kc + 1] = by;  Ass[r][kc + 1] = __uint_as_float(f2tf32(v.y - by));
            Asb[r][kc + 2] = bz;  Ass[r][kc + 2] = __uint_as_float(f2tf32(v.z - bz));
            Asb[r][kc + 3] = bw;  Ass[r][kc + 3] = __uint_as_float(f2tf32(v.w - bw));
        }
#pragma unroll
        for (int i = 0; i < 2; i++) {
            int fi = t + i * 256;
            int kr = fi >> 5;            // 32 float4 per row
            int cq = fi & 31;
            float4 v = *(const float4*)&B[(k0 + kr) * 128 + cq * 4];
            float bx = __uint_as_float(f2tf32(v.x));
            float by = __uint_as_float(f2tf32(v.y));
            float bz = __uint_as_float(f2tf32(v.z));
            float bw = __uint_as_float(f2tf32(v.w));
            int cc = cq * 4;
            Bsb[kr][cc + 0] = bx;  Bss[kr][cc + 0] = __uint_as_float(f2tf32(v.x - bx));
            Bsb[kr][cc + 1] = by;  Bss[kr][cc + 1] = __uint_as_float(f2tf32(v.y - by));
            Bsb[kr][cc + 2] = bz;  Bss[kr][cc + 2] = __uint_as_float(f2tf32(v.z - bz));
            Bsb[kr][cc + 3] = bw;  Bss[kr][cc + 3] = __uint_as_float(f2tf32(v.w - bw));
        }
        __syncthreads();

#pragma unroll
        for (int ks = 0; ks < 16; ks += 8) {
            uint32_t ab[2][4], as[2][4];
#pragma unroll
            for (int mt = 0; mt < 2; mt++) {
                int r0 = wr * 32 + mt * 16 + g;
                ab[mt][0] = __float_as_uint(Asb[r0][ks + tig]);
                ab[mt][1] = __float_as_uint(Asb[r0 + 8][ks + tig]);
                ab[mt][2] = __float_as_uint(Asb[r0][ks + tig + 4]);
                ab[mt][3] = __float_as_uint(Asb[r0 + 8][ks + tig + 4]);
                as[mt][0] = __float_as_uint(Ass[r0][ks + tig]);
                as[mt][1] = __float_as_uint(Ass[r0 + 8][ks + tig]);
                as[mt][2] = __float_as_uint(Ass[r0][ks + tig + 4]);
                as[mt][3] = __float_as_uint(Ass[r0 + 8][ks + tig + 4]);
            }
#pragma unroll
            for (int nt = 0; nt < 8; nt++) {
                int col = wc * 64 + nt * 8 + g;
                uint32_t bb0 = __float_as_uint(Bsb[ks + tig][col]);
                uint32_t bb1 = __float_as_uint(Bsb[ks + tig + 4][col]);
                uint32_t bs0 = __float_as_uint(Bss[ks + tig][col]);
                uint32_t bs1 = __float_as_uint(Bss[ks + tig + 4][col]);
#pragma unroll
                for (int mt = 0; mt < 2; mt++) {
                    MMA_TF32(c[mt][nt], ab[mt], bb0, bb1);   // hi*hi
                    MMA_TF32(c[mt][nt], as[mt], bb0, bb1);   // lo*hi
                    MMA_TF32(c[mt][nt], ab[mt], bs0, bs1);   // hi*lo
                }
            }
        }
        __syncthreads();
    }

    // epilogue: scale by dis[row], convert to fp16x2, write g_hsb
#pragma unroll
    for (int mt = 0; mt < 2; mt++) {
        int r0 = row0 + wr * 32 + mt * 16 + g;
        int r1 = r0 + 8;
        float d0 = (r0 < NN) ? g_dis[r0] : 0.0f;
        float d1 = (r1 < NN) ? g_dis[r1] : 0.0f;
#pragma unroll
        for (int nt = 0; nt < 8; nt++) {
            int colh = wc * 32 + nt * 4 + tig;   // fp16x2 index (pair of channels)
            if (r0 < NN)
                g_hsb[r0 * 64 + colh] = __floats2half2_rn(c[mt][nt][0] * d0,
                                                          c[mt][nt][1] * d0);
            if (r1 < NN)
                g_hsb[r1 * 64 + colh] = __floats2half2_rn(c[mt][nt][2] * d1,
                                                          c[mt][nt][3] * d1);
        }
    }
}

// ---------------- CSR pull aggregation: warp per node, 4-way unrolled ------
// agg[n] = dis[n] * (sum_{s in N(n)} hs[s] + hs[n]) + bias, fp32 accumulate.
// 4 independent accumulator sets raise gather MLP from ~2 to ~8.
__device__ __forceinline__ void acc_row(float& a0, float& a1, float& a2, float& a3,
                                        int s, int q) {
    uint2 v = *(const uint2*)(g_hsb + s * 64 + q * 2);
    float2 q0 = __half22float2(*reinterpret_cast<__half2*>(&v.x));
    float2 q1 = __half22float2(*reinterpret_cast<__half2*>(&v.y));
    a0 += q0.x; a1 += q0.y; a2 += q1.x; a3 += q1.y;
}

__global__ void k_aggregate(const float* __restrict__ bias) {
    int t = blockIdx.x * blockDim.x + threadIdx.x;
    int n = t >> 5, q = t & 31;
    if (n >= NN) return;
    int beg = g_rowptr[n], end = g_rowptr[n + 1];

    // accumulator set 0 starts with the self term
    float x0, x1, x2, x3;
    {
        uint2 u = *(const uint2*)(g_hsb + n * 64 + q * 2);
        float2 p0 = __half22float2(*reinterpret_cast<__half2*>(&u.x));
        float2 p1 = __half22float2(*reinterpret_cast<__half2*>(&u.y));
        x0 = p0.x; x1 = p0.y; x2 = p1.x; x3 = p1.y;
    }
    float y0 = 0.f, y1 = 0.f, y2 = 0.f, y3 = 0.f;
    float z0 = 0.f, z1 = 0.f, z2 = 0.f, z3 = 0.f;
    float w0 = 0.f, w1 = 0.f, w2 = 0.f, w3 = 0.f;

    int i = beg;
    for (; i + 3 < end; i += 4) {
        int s0 = g_csrsrc[i];
        int s1 = g_csrsrc[i + 1];
        int s2 = g_csrsrc[i + 2];
        int s3 = g_csrsrc[i + 3];
        acc_row(x0, x1, x2, x3, s0, q);
        acc_row(y0, y1, y2, y3, s1, q);
        acc_row(z0, z1, z2, z3, s2, q);
        acc_row(w0, w1, w2, w3, s3, q);
    }
    for (; i < end; i++) {
        int s = g_csrsrc[i];
        acc_row(x0, x1, x2, x3, s, q);
    }

    float a0 = (x0 + y0) + (z0 + w0);
    float a1 = (x1 + y1) + (z1 + w1);
    float a2 = (x2 + y2) + (z2 + w2);
    float a3 = (x3 + y3) + (z3 + w3);

    float d = g_dis[n];
    float4 b = ((const float4*)bias)[q];
    float4 acc;
    acc.x = a0 * d + b.x;
    acc.y = a1 * d + b.y;
    acc.z = a2 * d + b.z;
    acc.w = a3 * d + b.w;
    ((float4*)g_agg)[n * 32 + q] = acc;
}

// ---------------- BN stats (streaming) ----------------
__global__ void k_bnstats() {
    int c = threadIdx.x;
    float s = 0.0f, ss = 0.0f;
    for (int n = blockIdx.x; n < NN; n += gridDim.x) {
        float v = g_agg[n * HH + c];
        s += v;
        ss += v * v;
    }
    atomicAdd(&g_sum[c], s);
    atomicAdd(&g_sumsq[c], ss);
}

__global__ void k_bnfinal(const float* __restrict__ gamma, const float* __restrict__ beta) {
    int c = threadIdx.x;
    const float invN = 1.0f / (float)NN;
    float mu = g_sum[c] * invN;
    float var = g_sumsq[c] * invN - mu * mu;
    float sc = gamma[c] * rsqrtf(var + EPS);
    g_bnscale[c] = sc;
    g_bnshift[c] = beta[c] - mu * sc;
}

// ---------------- pooling (fused BN apply + relu) ----------------
__global__ void k_pool_zero() {
    int t = blockIdx.x * blockDim.x + threadIdx.x;
    if (t < GG * HH) g_pool[t] = 0.0f;
    if (t < GG) g_cnt[t] = 0.0f;
}

__global__ void k_pool(const int* __restrict__ batch) {
    int t = blockIdx.x * blockDim.x + threadIdx.x;
    int n = t >> 5, q = t & 31;
    if (n >= NN) return;
    int g = batch[n];
    float4 v  = ((const float4*)g_agg)[n * 32 + q];
    float4 sc = ((const float4*)g_bnscale)[q];
    float4 sh = ((const float4*)g_bnshift)[q];
    float4 o;
    o.x = fmaxf(v.x * sc.x + sh.x, 0.f);
    o.y = fmaxf(v.y * sc.y + sh.y, 0.f);
    o.z = fmaxf(v.z * sc.z + sh.z, 0.f);
    o.w = fmaxf(v.w * sc.w + sh.w, 0.f);
    float* out = g_pool + (size_t)g * HH + q * 4;
    asm volatile("red.global.add.v4.f32 [%0], {%1,%2,%3,%4};"
                 :: "l"(out), "f"(o.x), "f"(o.y), "f"(o.z), "f"(o.w)
                 : "memory");
    if (q == 0) atomicAdd(&g_cnt[g], 1.0f);
}

// ---------------- MLP head ----------------
__global__ void k_mlp(const float* __restrict__ w1, const float* __restrict__ b1,
                      const float* __restrict__ w2, const float* __restrict__ b2,
                      float* __restrict__ out) {
    int g = blockIdx.x;
    int t = threadIdx.x;       // 128
    __shared__ float p[128];
    __shared__ float red[4][8];
    float inv = 1.0f / fmaxf(g_cnt[g], 1.0f);
    p[t] = g_pool[g * HH + t] * inv;
    __syncthreads();
    float acc = b1[t];
#pragma unroll 8
    for (int k = 0; k < 128; k++) acc += p[k] * w1[k * 128 + t];
    float h = fmaxf(acc, 0.0f);
    float pr[CC];
#pragma unroll
    for (int c = 0; c < CC; c++) pr[c] = h * w2[t * CC + c];
#pragma unroll
    for (int off = 16; off > 0; off >>= 1)
#pragma unroll
        for (int c = 0; c < CC; c++) pr[c] += __shfl_down_sync(0xffffffffu, pr[c], off);
    int w = t >> 5, lane = t & 31;
    if (lane == 0)
#pragma unroll
        for (int c = 0; c < CC; c++) red[w][c] = pr[c];
    __syncthreads();
    if (t < CC) {
        out[g * CC + t] = red[0][t] + red[1][t] + red[2][t] + red[3][t] + b2[t];
    }
}

// ---------------- launch ----------------
extern "C" void kernel_launch(void* const* d_in, const int* in_sizes, int n_in,
                              void* d_out, int out_size) {
    const float* x      = (const float*)d_in[0];
    const int*   ei     = (const int*)d_in[1];
    const int*   batch  = (const int*)d_in[2];
    const float* conv_w = (const float*)d_in[3];
    const float* conv_b = (const float*)d_in[4];
    const float* bn_g   = (const float*)d_in[5];
    const float* bn_b   = (const float*)d_in[6];
    const float* w1     = (const float*)d_in[7];
    const float* b1     = (const float*)d_in[8];
    const float* w2     = (const float*)d_in[9];
    const float* b2     = (const float*)d_in[10];
    float* out = (float*)d_out;

    const int* src = ei;
    const int* dst = ei + EE;

    k_zero_degi<<<(NN + 255) / 256, 256>>>();
    k_deg_count<<<(EE + 255) / 256, 256>>>(dst);
    k_norm<<<(NN + 255) / 256, 256>>>();
    k_blocksum<<<NBLK, 256>>>();
    k_scanblocks<<<1, 256>>>();
    k_rowptr<<<NBLK, 256>>>();
    k_fill<<<(EE + 255) / 256, 256>>>(src, dst);

    const int ggrid = (NN + 127) / 128;    // 391
    const int nwarp_blocks = (int)(((long long)NN * 32 + 255) / 256);

    for (int l = 0; l < LL; l++) {
        const float* A = (l == 0) ? x : nullptr;   // nullptr -> g_agg with BN prologue
        k_gemm<<<ggrid, 256>>>(A, conv_w + (size_t)l * HH * HH, l > 0 ? 1 : 0);
        k_aggregate<<<nwarp_blocks, 256>>>(conv_b + (size_t)l * HH);
        k_bnstats<<<1024, 128>>>();
        k_bnfinal<<<1, 128>>>(bn_g + (size_t)l * HH, bn_b + (size_t)l * HH);
    }

    k_pool_zero<<<(GG * HH + 255) / 256, 256>>>();
    k_pool<<<nwarp_blocks, 256>>>(batch);
    k_mlp<<<GG, 128>>>(w1, b1, w2, b2, out);
}

// round 11
// speedup vs baseline: 1.1876x; 1.1876x over previous
#include <cuda_runtime.h>
#include <cuda_fp16.h>
#include <cstdint>

#define NN 50000
#define EE 800000
#define GG 1000
#define HH 128
#define LL 3
#define CC 6
#define EPS 1e-5f
#define NBLK 196                       // ceil(NN/256)

// ---------------- scratch (device globals; no allocation) ----------------
__device__ int   g_degi[NN];
__device__ int   g_blocksum[NBLK];
__device__ int   g_scancnt;
__device__ int   g_rowptr[NN + 1];
__device__ int   g_cursor[NN];
__device__ int   g_csrsrc[EE];
__device__ float g_dis[NN];
__device__ __half2 g_hsb[NN * 64];   // h * dis[row], fp16 packed
__device__ float g_agg[NN * HH];     // aggregated + self + bias (fp32)
__device__ float g_sum[HH];
__device__ float g_sumsq[HH];
__device__ float g_pool[GG * HH];
__device__ float g_cnt[GG];

// ---------------- degree / CSR build ----------------
__global__ void k_zero_degi() {
    int n = blockIdx.x * blockDim.x + threadIdx.x;
    if (n < NN) g_degi[n] = 0;
    if (n == 0) g_scancnt = 0;
}

__global__ void k_deg_count(const int* __restrict__ dst) {
    int e = blockIdx.x * blockDim.x + threadIdx.x;
    if (e < EE) atomicAdd(&g_degi[dst[e]], 1);
}

// merged: norm + blocksum + global scan (spin-sync) + rowptr/cursor
// 196 blocks x 256 threads; all blocks co-resident -> spin is safe.
__global__ void k_csr_mid() {
    __shared__ int sh[256];
    __shared__ int shb[256];
    int t = threadIdx.x;
    int b = blockIdx.x;
    int n = b * 256 + t;

    int deg = (n < NN) ? g_degi[n] : 0;
    if (n < NN) g_dis[n] = rsqrtf((float)deg + 1.0f);

    // local inclusive scan of degrees
    sh[t] = deg;
    __syncthreads();
#pragma unroll
    for (int off = 1; off < 256; off <<= 1) {
        int u = (t >= off) ? sh[t - off] : 0;
        __syncthreads();
        sh[t] += u;
        __syncthreads();
    }
    // publish block total, release, arrive
    if (t == 255) g_blocksum[b] = sh[255];
    __syncthreads();
    if (t == 0) {
        __threadfence();
        atomicAdd(&g_scancnt, 1);
        while (*(volatile int*)&g_scancnt < NBLK) { }
        __threadfence();
    }
    __syncthreads();

    // every block scans all 196 block sums locally
    int v = (t < NBLK) ? g_blocksum[t] : 0;
    shb[t] = v;
    __syncthreads();
#pragma unroll
    for (int off = 1; off < 256; off <<= 1) {
        int u = (t >= off) ? shb[t - off] : 0;
        __syncthreads();
        shb[t] += u;
        __syncthreads();
    }
    int blockoff = (b > 0) ? shb[b - 1] : 0;

    if (n < NN) {
        int excl = blockoff + sh[t] - deg;
        g_rowptr[n] = excl;
        g_cursor[n] = excl;
    }
    if (b == 0 && t == 0) g_rowptr[NN] = EE;
}

__global__ void k_fill(const int* __restrict__ src, const int* __restrict__ dst) {
    int e = blockIdx.x * blockDim.x + threadIdx.x;
    if (e < EE) {
        int d = dst[e];
        int pos = atomicAdd(&g_cursor[d], 1);
        g_csrsrc[pos] = src[e];
    }
}

// ---------------- TF32 helpers ----------------
__device__ __forceinline__ uint32_t f2tf32(float x) {
    uint32_t r;
    asm("cvt.rna.tf32.f32 %0, %1;" : "=r"(r) : "f"(x));
    return r;
}

#define MMA_TF32(C, A, B0, B1)                                                 \
    asm volatile("mma.sync.aligned.m16n8k8.row.col.f32.tf32.tf32.f32 "        \
                 "{%0,%1,%2,%3}, {%4,%5,%6,%7}, {%8,%9}, {%0,%1,%2,%3};"      \
                 : "+f"((C)[0]), "+f"((C)[1]), "+f"((C)[2]), "+f"((C)[3])     \
                 : "r"((A)[0]), "r"((A)[1]), "r"((A)[2]), "r"((A)[3]),        \
                   "r"(B0), "r"(B1))

// ---------------- GEMM: g_hsb = fp16( BN?(A)[N,128] @ B[128,128] * dis[row] )
// tf32 3-split tensor GEMM. BN scale/shift computed in-kernel from g_sum /
// g_sumsq + gamma/beta (replaces k_bnfinal).
#define AP 20     // A smem row stride
#define BP 136    // B smem row stride
__global__ void __launch_bounds__(256) k_gemm(const float* __restrict__ Ain,
                                              const float* __restrict__ B,
                                              const float* __restrict__ gamma,
                                              const float* __restrict__ beta,
                                              int apply_bn) {
    const float* __restrict__ A = Ain ? Ain : g_agg;
    __shared__ float Asb[128][AP];
    __shared__ float Ass[128][AP];
    __shared__ float Bsb[16][BP];
    __shared__ float Bss[16][BP];
    __shared__ __align__(16) float s_scale[128];
    __shared__ __align__(16) float s_shift[128];

    int row0 = blockIdx.x * 128;
    int t = threadIdx.x;
    if (apply_bn && t < 128) {
        const float invN = 1.0f / (float)NN;
        float mu = g_sum[t] * invN;
        float var = g_sumsq[t] * invN - mu * mu;
        float sc = gamma[t] * rsqrtf(var + EPS);
        s_scale[t] = sc;
        s_shift[t] = beta[t] - mu * sc;
    }
    __syncthreads();

    int w = t >> 5, lane = t & 31;
    int wr = w & 3, wc = w >> 2;
    int g = lane >> 2, tig = lane & 3;

    float c[2][8][4];
#pragma unroll
    for (int mt = 0; mt < 2; mt++)
#pragma unroll
        for (int nt = 0; nt < 8; nt++)
#pragma unroll
            for (int i = 0; i < 4; i++) c[mt][nt][i] = 0.0f;

    for (int k0 = 0; k0 < 128; k0 += 16) {
#pragma unroll
        for (int i = 0; i < 2; i++) {
            int fi = t + i * 256;        // 0..511
            int r = fi >> 2;             // 4 float4 per row
            int kq = fi & 3;
            int grow = row0 + r;
            float4 v = make_float4(0.f, 0.f, 0.f, 0.f);
            if (grow < NN) v = *(const float4*)&A[grow * 128 + k0 + kq * 4];
            if (apply_bn) {
                float4 sc = ((const float4*)s_scale)[(k0 >> 2) + kq];
                float4 sh = ((const float4*)s_shift)[(k0 >> 2) + kq];
                v.x = fmaxf(v.x * sc.x + sh.x, 0.f);
                v.y = fmaxf(v.y * sc.y + sh.y, 0.f);
                v.z = fmaxf(v.z * sc.z + sh.z, 0.f);
                v.w = fmaxf(v.w * sc.w + sh.w, 0.f);
            }
            float bx = __uint_as_float(f2tf32(v.x));
            float by = __uint_as_float(f2tf32(v.y));
            float bz = __uint_as_float(f2tf32(v.z));
            float bw = __uint_as_float(f2tf32(v.w));
            int kc = kq * 4;
            Asb[r][kc + 0] = bx;  Ass[r][kc + 0] = __uint_as_float(f2tf32(v.x - bx));
            Asb[r][kc + 1] = by;  Ass[r][kc + 1] = __uint_as_float(f2tf32(v.y - by));
            Asb[r][kc + 2] = bz;  Ass[r][kc + 2] = __uint_as_float(f2tf32(v.z - bz));
            Asb[r][kc + 3] = bw;  Ass[r][kc + 3] = __uint_as_float(f2tf32(v.w - bw));
        }
#pragma unroll
        for (int i = 0; i < 2; i++) {
            int fi = t + i * 256;
            int kr = fi >> 5;            // 32 float4 per row
            int cq = fi & 31;
            float4 v = *(const float4*)&B[(k0 + kr) * 128 + cq * 4];
            float bx = __uint_as_float(f2tf32(v.x));
            float by = __uint_as_float(f2tf32(v.y));
            float bz = __uint_as_float(f2tf32(v.z));
            float bw = __uint_as_float(f2tf32(v.w));
            int cc = cq * 4;
            Bsb[kr][cc + 0] = bx;  Bss[kr][cc + 0] = __uint_as_float(f2tf32(v.x - bx));
            Bsb[kr][cc + 1] = by;  Bss[kr][cc + 1] = __uint_as_float(f2tf32(v.y - by));
            Bsb[kr][cc + 2] = bz;  Bss[kr][cc + 2] = __uint_as_float(f2tf32(v.z - bz));
            Bsb[kr][cc + 3] = bw;  Bss[kr][cc + 3] = __uint_as_float(f2tf32(v.w - bw));
        }
        __syncthreads();

#pragma unroll
        for (int ks = 0; ks < 16; ks += 8) {
            uint32_t ab[2][4], as[2][4];
#pragma unroll
            for (int mt = 0; mt < 2; mt++) {
                int r0 = wr * 32 + mt * 16 + g;
                ab[mt][0] = __float_as_uint(Asb[r0][ks + tig]);
                ab[mt][1] = __float_as_uint(Asb[r0 + 8][ks + tig]);
                ab[mt][2] = __float_as_uint(Asb[r0][ks + tig + 4]);
                ab[mt][3] = __float_as_uint(Asb[r0 + 8][ks + tig + 4]);
                as[mt][0] = __float_as_uint(Ass[r0][ks + tig]);
                as[mt][1] = __float_as_uint(Ass[r0 + 8][ks + tig]);
                as[mt][2] = __float_as_uint(Ass[r0][ks + tig + 4]);
                as[mt][3] = __float_as_uint(Ass[r0 + 8][ks + tig + 4]);
            }
#pragma unroll
            for (int nt = 0; nt < 8; nt++) {
                int col = wc * 64 + nt * 8 + g;
                uint32_t bb0 = __float_as_uint(Bsb[ks + tig][col]);
                uint32_t bb1 = __float_as_uint(Bsb[ks + tig + 4][col]);
                uint32_t bs0 = __float_as_uint(Bss[ks + tig][col]);
                uint32_t bs1 = __float_as_uint(Bss[ks + tig + 4][col]);
#pragma unroll
                for (int mt = 0; mt < 2; mt++) {
                    MMA_TF32(c[mt][nt], ab[mt], bb0, bb1);   // hi*hi
                    MMA_TF32(c[mt][nt], as[mt], bb0, bb1);   // lo*hi
                    MMA_TF32(c[mt][nt], ab[mt], bs0, bs1);   // hi*lo
                }
            }
        }
        __syncthreads();
    }

    // epilogue: scale by dis[row], convert to fp16x2, write g_hsb
#pragma unroll
    for (int mt = 0; mt < 2; mt++) {
        int r0 = row0 + wr * 32 + mt * 16 + g;
        int r1 = r0 + 8;
        float d0 = (r0 < NN) ? g_dis[r0] : 0.0f;
        float d1 = (r1 < NN) ? g_dis[r1] : 0.0f;
#pragma unroll
        for (int nt = 0; nt < 8; nt++) {
            int colh = wc * 32 + nt * 4 + tig;   // fp16x2 index (pair of channels)
            if (r0 < NN)
                g_hsb[r0 * 64 + colh] = __floats2half2_rn(c[mt][nt][0] * d0,
                                                          c[mt][nt][1] * d0);
            if (r1 < NN)
                g_hsb[r1 * 64 + colh] = __floats2half2_rn(c[mt][nt][2] * d1,
                                                          c[mt][nt][3] * d1);
        }
    }
}

// ---------------- CSR pull aggregation: warp per node (R9 proven form) -----
// Block 0 zeroes BN stat accumulators (read later by k_bnstats; the GEMM that
// read the previous stats has already completed).
__global__ void k_aggregate(const float* __restrict__ bias) {
    int t = blockIdx.x * blockDim.x + threadIdx.x;
    if (blockIdx.x == 0 && threadIdx.x < 128) {
        g_sum[threadIdx.x] = 0.0f;
        g_sumsq[threadIdx.x] = 0.0f;
    }
    int n = t >> 5, q = t & 31;
    if (n >= NN) return;
    int beg = g_rowptr[n], end = g_rowptr[n + 1];

    uint2 u = *(const uint2*)(g_hsb + n * 64 + q * 2);   // self term
    float2 p0 = __half22float2(*reinterpret_cast<__half2*>(&u.x));
    float2 p1 = __half22float2(*reinterpret_cast<__half2*>(&u.y));
    float a0 = p0.x, a1 = p0.y, a2 = p1.x, a3 = p1.y;

    for (int i = beg; i < end; i++) {
        int s = g_csrsrc[i];                              // warp-uniform broadcast
        uint2 v = *(const uint2*)(g_hsb + s * 64 + q * 2);
        float2 q0 = __half22float2(*reinterpret_cast<__half2*>(&v.x));
        float2 q1 = __half22float2(*reinterpret_cast<__half2*>(&v.y));
        a0 += q0.x; a1 += q0.y; a2 += q1.x; a3 += q1.y;
    }
    float d = g_dis[n];
    float4 b = ((const float4*)bias)[q];
    float4 acc;
    acc.x = a0 * d + b.x;
    acc.y = a1 * d + b.y;
    acc.z = a2 * d + b.z;
    acc.w = a3 * d + b.w;
    ((float4*)g_agg)[n * 32 + q] = acc;
}

// ---------------- BN stats (streaming); also zeroes pool buffers ----------
__global__ void k_bnstats() {
    int c = threadIdx.x;
    // fold pool zeroing in (idempotent; k_pool runs only after last bnstats)
    int zt = blockIdx.x * blockDim.x + c;
    if (zt < GG * HH) g_pool[zt] = 0.0f;
    if (zt < GG) g_cnt[zt] = 0.0f;

    float s = 0.0f, ss = 0.0f;
    for (int n = blockIdx.x; n < NN; n += gridDim.x) {
        float v = g_agg[n * HH + c];
        s += v;
        ss += v * v;
    }
    atomicAdd(&g_sum[c], s);
    atomicAdd(&g_sumsq[c], ss);
}

// ---------------- pooling (BN apply + relu, scale/shift from raw stats) ----
__global__ void k_pool(const int* __restrict__ batch,
                       const float* __restrict__ gamma,
                       const float* __restrict__ beta) {
    int t = blockIdx.x * blockDim.x + threadIdx.x;
    int n = t >> 5, q = t & 31;
    if (n >= NN) return;
    int g = batch[n];
    const float invN = 1.0f / (float)NN;
    float4 v = ((const float4*)g_agg)[n * 32 + q];
    float4 sm = ((const float4*)g_sum)[q];
    float4 sq = ((const float4*)g_sumsq)[q];
    float4 ga = ((const float4*)gamma)[q];
    float4 be = ((const float4*)beta)[q];
    float4 o;
    {
        float mu = sm.x * invN; float var = sq.x * invN - mu * mu;
        float sc = ga.x * rsqrtf(var + EPS);
        o.x = fmaxf(v.x * sc + (be.x - mu * sc), 0.f);
    }
    {
        float mu = sm.y * invN; float var = sq.y * invN - mu * mu;
        float sc = ga.y * rsqrtf(var + EPS);
        o.y = fmaxf(v.y * sc + (be.y - mu * sc), 0.f);
    }
    {
        float mu = sm.z * invN; float var = sq.z * invN - mu * mu;
        float sc = ga.z * rsqrtf(var + EPS);
        o.z = fmaxf(v.z * sc + (be.z - mu * sc), 0.f);
    }
    {
        float mu = sm.w * invN; float var = sq.w * invN - mu * mu;
        float sc = ga.w * rsqrtf(var + EPS);
        o.w = fmaxf(v.w * sc + (be.w - mu * sc), 0.f);
    }
    float* out = g_pool + (size_t)g * HH + q * 4;
    asm volatile("red.global.add.v4.f32 [%0], {%1,%2,%3,%4};"
                 :: "l"(out), "f"(o.x), "f"(o.y), "f"(o.z), "f"(o.w)
                 : "memory");
    if (q == 0) atomicAdd(&g_cnt[g], 1.0f);
}

// ---------------- MLP head ----------------
__global__ void k_mlp(const float* __restrict__ w1, const float* __restrict__ b1,
                      const float* __restrict__ w2, const float* __restrict__ b2,
                      float* __restrict__ out) {
    int g = blockIdx.x;
    int t = threadIdx.x;       // 128
    __shared__ float p[128];
    __shared__ float red[4][8];
    float inv = 1.0f / fmaxf(g_cnt[g], 1.0f);
    p[t] = g_pool[g * HH + t] * inv;
    __syncthreads();
    float acc = b1[t];
#pragma unroll 8
    for (int k = 0; k < 128; k++) acc += p[k] * w1[k * 128 + t];
    float h = fmaxf(acc, 0.0f);
    float pr[CC];
#pragma unroll
    for (int c = 0; c < CC; c++) pr[c] = h * w2[t * CC + c];
#pragma unroll
    for (int off = 16; off > 0; off >>= 1)
#pragma unroll
        for (int c = 0; c < CC; c++) pr[c] += __shfl_down_sync(0xffffffffu, pr[c], off);
    int w = t >> 5, lane = t & 31;
    if (lane == 0)
#pragma unroll
        for (int c = 0; c < CC; c++) red[w][c] = pr[c];
    __syncthreads();
    if (t < CC) {
        out[g * CC + t] = red[0][t] + red[1][t] + red[2][t] + red[3][t] + b2[t];
    }
}

// ---------------- launch ----------------
extern "C" void kernel_launch(void* const* d_in, const int* in_sizes, int n_in,
                              void* d_out, int out_size) {
    const float* x      = (const float*)d_in[0];
    const int*   ei     = (const int*)d_in[1];
    const int*   batch  = (const int*)d_in[2];
    const float* conv_w = (const float*)d_in[3];
    const float* conv_b = (const float*)d_in[4];
    const float* bn_g   = (const float*)d_in[5];
    const float* bn_b   = (const float*)d_in[6];
    const float* w1     = (const float*)d_in[7];
    const float* b1     = (const float*)d_in[8];
    const float* w2     = (const float*)d_in[9];
    const float* b2     = (const float*)d_in[10];
    float* out = (float*)d_out;

    const int* src = ei;
    const int* dst = ei + EE;

    k_zero_degi<<<(NN + 255) / 256, 256>>>();
    k_deg_count<<<(EE + 255) / 256, 256>>>(dst);
    k_csr_mid<<<NBLK, 256>>>();
    k_fill<<<(EE + 255) / 256, 256>>>(src, dst);

    const int ggrid = (NN + 127) / 128;    // 391
    const int nwarp_blocks = (int)(((long long)NN * 32 + 255) / 256);

    for (int l = 0; l < LL; l++) {
        const float* A = (l == 0) ? x : nullptr;   // nullptr -> g_agg with BN prologue
        const float* ga = (l > 0) ? bn_g + (size_t)(l - 1) * HH : nullptr;
        const float* be = (l > 0) ? bn_b + (size_t)(l - 1) * HH : nullptr;
        k_gemm<<<ggrid, 256>>>(A, conv_w + (size_t)l * HH * HH, ga, be, l > 0 ? 1 : 0);
        k_aggregate<<<nwarp_blocks, 256>>>(conv_b + (size_t)l * HH);
        k_bnstats<<<1024, 128>>>();
    }

    k_pool<<<nwarp_blocks, 256>>>(batch, bn_g + (size_t)(LL - 1) * HH,
                                  bn_b + (size_t)(LL - 1) * HH);
    k_mlp<<<GG, 128>>>(w1, b1, w2, b2, out);
}

// round 12
// speedup vs baseline: 1.5133x; 1.2742x over previous
#include <cuda_runtime.h>
#include <cuda_fp16.h>
#include <cstdint>

#define NN 50000
#define EE 800000
#define GG 1000
#define HH 128
#define LL 3
#define CC 6
#define EPS 1e-5f
#define NBLK 196                       // ceil(NN/256)

// ---------------- scratch (device globals; no allocation) ----------------
__device__ int   g_degi[NN];
__device__ int   g_blocksum[NBLK];
__device__ int   g_scancnt;
__device__ int   g_rowptr[NN + 1];
__device__ int   g_cursor[NN];
__device__ int   g_csrsrc[EE];
__device__ float g_dis[NN];
__device__ __half2 g_hsb[NN * 64];   // h * dis[row], fp16 packed
__device__ float g_agg[NN * HH];     // aggregated + self + bias (fp32)
__device__ float g_sum[HH];
__device__ float g_sumsq[HH];
__device__ float g_pool[GG * HH];
__device__ float g_cnt[GG];

// ---------------- degree / CSR build ----------------
__global__ void k_zero_degi() {
    int n = blockIdx.x * blockDim.x + threadIdx.x;
    if (n < NN) g_degi[n] = 0;
    if (n == 0) g_scancnt = 0;
}

__global__ void k_deg_count(const int* __restrict__ dst) {
    int e = blockIdx.x * blockDim.x + threadIdx.x;
    if (e < EE) atomicAdd(&g_degi[dst[e]], 1);
}

// merged: norm + blocksum + global scan (spin-sync) + rowptr/cursor
__global__ void k_csr_mid() {
    __shared__ int sh[256];
    __shared__ int shb[256];
    int t = threadIdx.x;
    int b = blockIdx.x;
    int n = b * 256 + t;

    int deg = (n < NN) ? g_degi[n] : 0;
    if (n < NN) g_dis[n] = rsqrtf((float)deg + 1.0f);

    sh[t] = deg;
    __syncthreads();
#pragma unroll
    for (int off = 1; off < 256; off <<= 1) {
        int u = (t >= off) ? sh[t - off] : 0;
        __syncthreads();
        sh[t] += u;
        __syncthreads();
    }
    if (t == 255) g_blocksum[b] = sh[255];
    __syncthreads();
    if (t == 0) {
        __threadfence();
        atomicAdd(&g_scancnt, 1);
        while (*(volatile int*)&g_scancnt < NBLK) { }
        __threadfence();
    }
    __syncthreads();

    int v = (t < NBLK) ? g_blocksum[t] : 0;
    shb[t] = v;
    __syncthreads();
#pragma unroll
    for (int off = 1; off < 256; off <<= 1) {
        int u = (t >= off) ? shb[t - off] : 0;
        __syncthreads();
        shb[t] += u;
        __syncthreads();
    }
    int blockoff = (b > 0) ? shb[b - 1] : 0;

    if (n < NN) {
        int excl = blockoff + sh[t] - deg;
        g_rowptr[n] = excl;
        g_cursor[n] = excl;
    }
    if (b == 0 && t == 0) g_rowptr[NN] = EE;
}

__global__ void k_fill(const int* __restrict__ src, const int* __restrict__ dst) {
    int e = blockIdx.x * blockDim.x + threadIdx.x;
    if (e < EE) {
        int d = dst[e];
        int pos = atomicAdd(&g_cursor[d], 1);
        g_csrsrc[pos] = src[e];
    }
}

// ---------------- fp16 MMA helpers ----------------
#define MMA_F16(C, A, B0, B1)                                                  \
    asm volatile("mma.sync.aligned.m16n8k16.row.col.f32.f16.f16.f32 "         \
                 "{%0,%1,%2,%3}, {%4,%5,%6,%7}, {%8,%9}, {%0,%1,%2,%3};"      \
                 : "+f"((C)[0]), "+f"((C)[1]), "+f"((C)[2]), "+f"((C)[3])     \
                 : "r"((A)[0]), "r"((A)[1]), "r"((A)[2]), "r"((A)[3]),        \
                   "r"(B0), "r"(B1))

__device__ __forceinline__ uint32_t smem_u32(const void* p) {
    return (uint32_t)__cvta_generic_to_shared(p);
}

// ---------------- GEMM: g_hsb = fp16( BN?(A)[N,128] @ B[128,128] * dis[row] )
// fp16 tensor MMA (m16n8k16), fp32 accumulate. Block 128x128, 8 warps (4x2).
// BN scale/shift computed in-kernel from g_sum/g_sumsq + gamma/beta.
#define APH 24    // A smem row stride (halves)
#define BPH 136   // B smem row stride (halves)
__global__ void __launch_bounds__(256) k_gemm(const float* __restrict__ Ain,
                                              const float* __restrict__ B,
                                              const float* __restrict__ gamma,
                                              const float* __restrict__ beta,
                                              int apply_bn) {
    const float* __restrict__ A = Ain ? Ain : g_agg;
    __shared__ __half Ah[128][APH];     // [row][k-chunk 16 + pad]
    __shared__ __half Bh[16][BPH];      // [k][col 128 + pad]
    __shared__ __align__(16) float s_scale[128];
    __shared__ __align__(16) float s_shift[128];

    int row0 = blockIdx.x * 128;
    int t = threadIdx.x;
    if (apply_bn && t < 128) {
        const float invN = 1.0f / (float)NN;
        float mu = g_sum[t] * invN;
        float var = g_sumsq[t] * invN - mu * mu;
        float sc = gamma[t] * rsqrtf(var + EPS);
        s_scale[t] = sc;
        s_shift[t] = beta[t] - mu * sc;
    }
    __syncthreads();

    int w = t >> 5, lane = t & 31;
    int wr = w & 3, wc = w >> 2;        // warp tile: rows wr*32, cols wc*64
    int g = lane >> 2, tig = lane & 3;

    // A-stage indexing: thread covers row ar, k-quad akq (per chunk 128x16)
    int ar = t >> 1, akq = t & 1;       // 2 float4 per row? no: 128*16/4=512 f4, 2/thread
    // use fi mapping instead below

    // ldmatrix address precompute
    int g4 = lane >> 3, li = lane & 7;
    int arow_off = (g4 & 1) * 8 + li;   // within warp A tile
    int akoff = (g4 >> 1) * 8;
    int blrow = lane & 15;              // B ldmatrix source row (k)

    float c[2][8][4];
#pragma unroll
    for (int mt = 0; mt < 2; mt++)
#pragma unroll
        for (int nt = 0; nt < 8; nt++)
#pragma unroll
            for (int i = 0; i < 4; i++) c[mt][nt][i] = 0.0f;

    for (int k0 = 0; k0 < 128; k0 += 16) {
        // ---- stage A chunk: 128 rows x 16 k (512 float4, 2/thread) ----
#pragma unroll
        for (int i = 0; i < 2; i++) {
            int fi = t + i * 256;        // 0..511
            int r = fi >> 2;             // 4 float4 per row
            int kq = fi & 3;
            int grow = row0 + r;
            float4 v = make_float4(0.f, 0.f, 0.f, 0.f);
            if (grow < NN) v = *(const float4*)&A[grow * 128 + k0 + kq * 4];
            if (apply_bn) {
                float4 sc = ((const float4*)s_scale)[(k0 >> 2) + kq];
                float4 sh = ((const float4*)s_shift)[(k0 >> 2) + kq];
                v.x = fmaxf(v.x * sc.x + sh.x, 0.f);
                v.y = fmaxf(v.y * sc.y + sh.y, 0.f);
                v.z = fmaxf(v.z * sc.z + sh.z, 0.f);
                v.w = fmaxf(v.w * sc.w + sh.w, 0.f);
            }
            __half2 h0 = __floats2half2_rn(v.x, v.y);
            __half2 h1 = __floats2half2_rn(v.z, v.w);
            *(__half2*)&Ah[r][kq * 4]     = h0;
            *(__half2*)&Ah[r][kq * 4 + 2] = h1;
        }
        // ---- stage B chunk: 16 k x 128 cols (512 float4, 2/thread) ----
#pragma unroll
        for (int i = 0; i < 2; i++) {
            int fi = t + i * 256;
            int kr = fi >> 5;            // 32 float4 per row
            int cq = fi & 31;
            float4 v = *(const float4*)&B[(k0 + kr) * 128 + cq * 4];
            __half2 h0 = __floats2half2_rn(v.x, v.y);
            __half2 h1 = __floats2half2_rn(v.z, v.w);
            *(__half2*)&Bh[kr][cq * 4]     = h0;
            *(__half2*)&Bh[kr][cq * 4 + 2] = h1;
        }
        __syncthreads();

        // ---- MMA: 2 mt x 8 nt per warp ----
        uint32_t afr[2][4];
#pragma unroll
        for (int mt = 0; mt < 2; mt++) {
            uint32_t aaddr = smem_u32(&Ah[wr * 32 + mt * 16 + arow_off][akoff]);
            asm volatile("ldmatrix.sync.aligned.m8n8.x4.shared.b16 "
                         "{%0,%1,%2,%3}, [%4];"
                         : "=r"(afr[mt][0]), "=r"(afr[mt][1]),
                           "=r"(afr[mt][2]), "=r"(afr[mt][3])
                         : "r"(aaddr));
        }
#pragma unroll
        for (int nt = 0; nt < 8; nt++) {
            int colbase = wc * 64 + nt * 8;
            uint32_t baddr = smem_u32(&Bh[blrow][colbase]);
            uint32_t b0, b1;
            asm volatile("ldmatrix.sync.aligned.m8n8.x2.trans.shared.b16 "
                         "{%0,%1}, [%2];"
                         : "=r"(b0), "=r"(b1)
                         : "r"(baddr));
#pragma unroll
            for (int mt = 0; mt < 2; mt++)
                MMA_F16(c[mt][nt], afr[mt], b0, b1);
        }
        __syncthreads();
    }

    // epilogue: scale by dis[row], convert to fp16x2, write g_hsb
#pragma unroll
    for (int mt = 0; mt < 2; mt++) {
        int r0 = row0 + wr * 32 + mt * 16 + g;
        int r1 = r0 + 8;
        float d0 = (r0 < NN) ? g_dis[r0] : 0.0f;
        float d1 = (r1 < NN) ? g_dis[r1] : 0.0f;
#pragma unroll
        for (int nt = 0; nt < 8; nt++) {
            int colh = wc * 32 + nt * 4 + tig;   // fp16x2 index (pair of channels)
            if (r0 < NN)
                g_hsb[r0 * 64 + colh] = __floats2half2_rn(c[mt][nt][0] * d0,
                                                          c[mt][nt][1] * d0);
            if (r1 < NN)
                g_hsb[r1 * 64 + colh] = __floats2half2_rn(c[mt][nt][2] * d1,
                                                          c[mt][nt][3] * d1);
        }
    }
}

// ---------------- CSR pull aggregation: warp per node ----------------------
// Block 0 zeroes BN stat accumulators.
__global__ void k_aggregate(const float* __restrict__ bias) {
    int t = blockIdx.x * blockDim.x + threadIdx.x;
    if (blockIdx.x == 0 && threadIdx.x < 128) {
        g_sum[threadIdx.x] = 0.0f;
        g_sumsq[threadIdx.x] = 0.0f;
    }
    int n = t >> 5, q = t & 31;
    if (n >= NN) return;
    int beg = g_rowptr[n], end = g_rowptr[n + 1];

    uint2 u = *(const uint2*)(g_hsb + n * 64 + q * 2);   // self term
    float2 p0 = __half22float2(*reinterpret_cast<__half2*>(&u.x));
    float2 p1 = __half22float2(*reinterpret_cast<__half2*>(&u.y));
    float a0 = p0.x, a1 = p0.y, a2 = p1.x, a3 = p1.y;

    for (int i = beg; i < end; i++) {
        int s = g_csrsrc[i];                              // warp-uniform broadcast
        uint2 v = *(const uint2*)(g_hsb + s * 64 + q * 2);
        float2 q0 = __half22float2(*reinterpret_cast<__half2*>(&v.x));
        float2 q1 = __half22float2(*reinterpret_cast<__half2*>(&v.y));
        a0 += q0.x; a1 += q0.y; a2 += q1.x; a3 += q1.y;
    }
    float d = g_dis[n];
    float4 b = ((const float4*)bias)[q];
    float4 acc;
    acc.x = a0 * d + b.x;
    acc.y = a1 * d + b.y;
    acc.z = a2 * d + b.z;
    acc.w = a3 * d + b.w;
    ((float4*)g_agg)[n * 32 + q] = acc;
}

// ---------------- BN stats (streaming); also zeroes pool buffers ----------
__global__ void k_bnstats() {
    int c = threadIdx.x;
    int zt = blockIdx.x * blockDim.x + c;
    if (zt < GG * HH) g_pool[zt] = 0.0f;
    if (zt < GG) g_cnt[zt] = 0.0f;

    float s = 0.0f, ss = 0.0f;
    for (int n = blockIdx.x; n < NN; n += gridDim.x) {
        float v = g_agg[n * HH + c];
        s += v;
        ss += v * v;
    }
    atomicAdd(&g_sum[c], s);
    atomicAdd(&g_sumsq[c], ss);
}

// ---------------- pooling (BN apply + relu from raw stats) ----------------
__global__ void k_pool(const int* __restrict__ batch,
                       const float* __restrict__ gamma,
                       const float* __restrict__ beta) {
    int t = blockIdx.x * blockDim.x + threadIdx.x;
    int n = t >> 5, q = t & 31;
    if (n >= NN) return;
    int g = batch[n];
    const float invN = 1.0f / (float)NN;
    float4 v = ((const float4*)g_agg)[n * 32 + q];
    float4 sm = ((const float4*)g_sum)[q];
    float4 sq = ((const float4*)g_sumsq)[q];
    float4 ga = ((const float4*)gamma)[q];
    float4 be = ((const float4*)beta)[q];
    float4 o;
    {
        float mu = sm.x * invN; float var = sq.x * invN - mu * mu;
        float sc = ga.x * rsqrtf(var + EPS);
        o.x = fmaxf(v.x * sc + (be.x - mu * sc), 0.f);
    }
    {
        float mu = sm.y * invN; float var = sq.y * invN - mu * mu;
        float sc = ga.y * rsqrtf(var + EPS);
        o.y = fmaxf(v.y * sc + (be.y - mu * sc), 0.f);
    }
    {
        float mu = sm.z * invN; float var = sq.z * invN - mu * mu;
        float sc = ga.z * rsqrtf(var + EPS);
        o.z = fmaxf(v.z * sc + (be.z - mu * sc), 0.f);
    }
    {
        float mu = sm.w * invN; float var = sq.w * invN - mu * mu;
        float sc = ga.w * rsqrtf(var + EPS);
        o.w = fmaxf(v.w * sc + (be.w - mu * sc), 0.f);
    }
    float* out = g_pool + (size_t)g * HH + q * 4;
    asm volatile("red.global.add.v4.f32 [%0], {%1,%2,%3,%4};"
                 :: "l"(out), "f"(o.x), "f"(o.y), "f"(o.z), "f"(o.w)
                 : "memory");
    if (q == 0) atomicAdd(&g_cnt[g], 1.0f);
}

// ---------------- MLP head ----------------
__global__ void k_mlp(const float* __restrict__ w1, const float* __restrict__ b1,
                      const float* __restrict__ w2, const float* __restrict__ b2,
                      float* __restrict__ out) {
    int g = blockIdx.x;
    int t = threadIdx.x;       // 128
    __shared__ float p[128];
    __shared__ float red[4][8];
    float inv = 1.0f / fmaxf(g_cnt[g], 1.0f);
    p[t] = g_pool[g * HH + t] * inv;
    __syncthreads();
    float acc = b1[t];
#pragma unroll 8
    for (int k = 0; k < 128; k++) acc += p[k] * w1[k * 128 + t];
    float h = fmaxf(acc, 0.0f);
    float pr[CC];
#pragma unroll
    for (int c = 0; c < CC; c++) pr[c] = h * w2[t * CC + c];
#pragma unroll
    for (int off = 16; off > 0; off >>= 1)
#pragma unroll
        for (int c = 0; c < CC; c++) pr[c] += __shfl_down_sync(0xffffffffu, pr[c], off);
    int w = t >> 5, lane = t & 31;
    if (lane == 0)
#pragma unroll
        for (int c = 0; c < CC; c++) red[w][c] = pr[c];
    __syncthreads();
    if (t < CC) {
        out[g * CC + t] = red[0][t] + red[1][t] + red[2][t] + red[3][t] + b2[t];
    }
}

// ---------------- launch ----------------
extern "C" void kernel_launch(void* const* d_in, const int* in_sizes, int n_in,
                              void* d_out, int out_size) {
    const float* x      = (const float*)d_in[0];
    const int*   ei     = (const int*)d_in[1];
    const int*   batch  = (const int*)d_in[2];
    const float* conv_w = (const float*)d_in[3];
    const float* conv_b = (const float*)d_in[4];
    const float* bn_g   = (const float*)d_in[5];
    const float* bn_b   = (const float*)d_in[6];
    const float* w1     = (const float*)d_in[7];
    const float* b1     = (const float*)d_in[8];
    const float* w2     = (const float*)d_in[9];
    const float* b2     = (const float*)d_in[10];
    float* out = (float*)d_out;

    const int* src = ei;
    const int* dst = ei + EE;

    k_zero_degi<<<(NN + 255) / 256, 256>>>();
    k_deg_count<<<(EE + 255) / 256, 256>>>(dst);
    k_csr_mid<<<NBLK, 256>>>();
    k_fill<<<(EE + 255) / 256, 256>>>(src, dst);

    const int ggrid = (NN + 127) / 128;    // 391
    const int nwarp_blocks = (int)(((long long)NN * 32 + 255) / 256);

    for (int l = 0; l < LL; l++) {
        const float* A = (l == 0) ? x : nullptr;   // nullptr -> g_agg with BN prologue
        const float* ga = (l > 0) ? bn_g + (size_t)(l - 1) * HH : nullptr;
        const float* be = (l > 0) ? bn_b + (size_t)(l - 1) * HH : nullptr;
        k_gemm<<<ggrid, 256>>>(A, conv_w + (size_t)l * HH * HH, ga, be, l > 0 ? 1 : 0);
        k_aggregate<<<nwarp_blocks, 256>>>(conv_b + (size_t)l * HH);
        k_bnstats<<<1024, 128>>>();
    }

    k_pool<<<nwarp_blocks, 256>>>(batch, bn_g + (size_t)(LL - 1) * HH,
                                  bn_b + (size_t)(LL - 1) * HH);
    k_mlp<<<GG, 128>>>(w1, b1, w2, b2, out);
}